// round 12
// baseline (speedup 1.0000x reference)
#include <cuda_runtime.h>
#include <cstdint>

// ---------------------------------------------------------------------------
// Inverse NTT over F_P, P = 2013265921 = 15*2^27 + 1, N = 2^22, C = 4.
// int32 inputs, float32 output (confirmed rel_err == 0).
//
// Two-phase NTT.  Radix-4 passes (4 uint4 live -> ~40 regs -> 3 CTAs/SM),
// two unroll-1 iterations per pass; final radix-2 fused with the gmem seam.
//   phase 1: staged gather | R4(1,2) R4(3,4) R4(5,6) R4(7,8) R4(9,10) |
//            R2(11)+paired scratch store
//   phase 2: prefetch | load+twist+R4(1,2) R4(3,4) R4(5,6) R4(7,8) R4(9,10) |
//            R2(11)+output
// Swizzle SZ(p) = p ^ ((p>>3)&7) ^ ((p>>2)&4): verified conflict-free for all
// lane patterns (slot strides 1/2/4/8 and the two special passes).
// ---------------------------------------------------------------------------

#define LOGN 22
#define NN   (1u << LOGN)
#define NH   (1u << (LOGN - 1))

static constexpr unsigned int P        = 2013265921u;
static constexpr unsigned int PINV_NEG = 2013265919u;                  // -P^{-1} mod 2^32
static constexpr unsigned long long Rmod = (1ull << 32) % P;
static constexpr unsigned int R2C = (unsigned int)((Rmod * Rmod) % P); // 2^64 mod P

// Scratch: phase-1 tile b, slot v at ((v&1023)<<11 + b)*2 + (v>>10).
static __device__ uint4 g_scratch[NN];   // 64 MB

__device__ __forceinline__ unsigned int SZ(unsigned int p) {
    return p ^ ((p >> 3) & 7u) ^ ((p >> 2) & 4u);
}
__device__ __forceinline__ unsigned int mulmont(unsigned int a, unsigned int bR) {
    unsigned long long t = (unsigned long long)a * bR;
    unsigned int m = (unsigned int)t * PINV_NEG;
    unsigned long long s = t + (unsigned long long)m * P;
    unsigned int r = (unsigned int)(s >> 32);
    return (r >= P) ? r - P : r;
}
__device__ __forceinline__ unsigned int addmod(unsigned int a, unsigned int b) {
    unsigned int r = a + b;  return min(r, r - P);
}
__device__ __forceinline__ unsigned int submod(unsigned int a, unsigned int b) {
    unsigned int r = a - b;  return min(r, r + P);
}
__device__ __forceinline__ void bflyT(uint4& lo, uint4& hi, unsigned int T) {
    unsigned int t0 = mulmont(hi.x, T), t1 = mulmont(hi.y, T);
    unsigned int t2 = mulmont(hi.z, T), t3 = mulmont(hi.w, T);
    uint4 l = lo;
    lo = make_uint4(addmod(l.x, t0), addmod(l.y, t1), addmod(l.z, t2), addmod(l.w, t3));
    hi = make_uint4(submod(l.x, t0), submod(l.y, t1), submod(l.z, t2), submod(l.w, t3));
}
__device__ __forceinline__ void bfly1(uint4& lo, uint4& hi) {
    uint4 l = lo, h = hi;
    lo = make_uint4(addmod(l.x, h.x), addmod(l.y, h.y), addmod(l.z, h.z), addmod(l.w, h.w));
    hi = make_uint4(submod(l.x, h.x), submod(l.y, h.y), submod(l.z, h.z), submod(l.w, h.w));
}

// ---------------------------------------------------------------------------
// Phase 1: gather + stages 1..11 on two 2048-slot tiles (bit-reversed storage).
// Stage s acts on storage bit 11-s.  Pass (s,s+1): quad base p has bits
// (11-s),(10-s) clear; q = rev_{s-1}(p >> (12-s)); i = q << (10-s);
// T_s = shtw[i<<1], T_{s+1} = shtw[i] / shtw[i+512].
// ---------------------------------------------------------------------------
__global__ void __launch_bounds__(512, 3) k_stage1(const uint4* __restrict__ in,
                                                   const unsigned int* __restrict__ tw) {
    extern __shared__ uint4 smem[];                 // 2 tiles of 2048 + shtw
    unsigned int* shtw = (unsigned int*)(smem + 4096);

    const unsigned int tid = threadIdx.x;
    const unsigned int rb0 = 2u * blockIdx.x;
    const unsigned int jt  = tid >> 8, m = tid & 255u;
    const unsigned int tb  = jt << 11;

    shtw[tid]        = mulmont(tw[(size_t)tid << 11], R2C);
    shtw[tid + 512u] = mulmont(tw[(size_t)(tid + 512u) << 11], R2C);

    // staged gather: 32B per thread-row (both tiles)
    #pragma unroll
    for (int r = 0; r < 4; r++) {
        unsigned int p = tid + r * 512u;
        size_t row = ((size_t)p << 11) | rb0;
        smem[SZ(p)]         = in[row];
        smem[2048u + SZ(p)] = in[row + 1];
    }
    __syncthreads();

    const unsigned int J = shtw[512];

    // ---- P1: stages 1,2 (bits 10,9) -------------------------------------
    #pragma unroll 1
    for (int it = 0; it < 2; it++) {
        unsigned int u = m + ((unsigned)it << 8);           // [0,512)
        uint4 x0 = smem[tb + SZ(u)],         x1 = smem[tb + SZ(u + 512u)];
        uint4 x2 = smem[tb + SZ(u + 1024u)], x3 = smem[tb + SZ(u + 1536u)];
        bfly1(x0, x2); bfly1(x1, x3);                       // s=1 (bit 10), T=1
        bfly1(x0, x1); bflyT(x2, x3, J);                    // s=2 (bit 9)
        smem[tb + SZ(u)] = x0;         smem[tb + SZ(u + 512u)]  = x1;
        smem[tb + SZ(u + 1024u)] = x2; smem[tb + SZ(u + 1536u)] = x3;
    }
    __syncthreads();

    // ---- P2: stages 3,4 (bits 8,7) --------------------------------------
    #pragma unroll 1
    for (int it = 0; it < 2; it++) {
        unsigned int u = m + ((unsigned)it << 8);
        unsigned int low = u & 127u, high = u >> 7;         // high < 4
        unsigned int p = (high << 9) | low;
        unsigned int i = (__brev(high) >> 30) << 7;
        unsigned int Ts = shtw[i << 1], Tl = shtw[i], Th = shtw[i + 512u];
        uint4 x0 = smem[tb + SZ(p)],        x1 = smem[tb + SZ(p + 128u)];
        uint4 x2 = smem[tb + SZ(p + 256u)], x3 = smem[tb + SZ(p + 384u)];
        bflyT(x0, x2, Ts); bflyT(x1, x3, Ts);
        bflyT(x0, x1, Tl); bflyT(x2, x3, Th);
        smem[tb + SZ(p)] = x0;        smem[tb + SZ(p + 128u)] = x1;
        smem[tb + SZ(p + 256u)] = x2; smem[tb + SZ(p + 384u)] = x3;
    }
    __syncthreads();

    // ---- P3: stages 5,6 (bits 6,5) --------------------------------------
    #pragma unroll 1
    for (int it = 0; it < 2; it++) {
        unsigned int u = m + ((unsigned)it << 8);
        unsigned int low = u & 31u, high = u >> 5;          // high < 16
        unsigned int p = (high << 7) | low;
        unsigned int i = (__brev(high) >> 28) << 5;
        unsigned int Ts = shtw[i << 1], Tl = shtw[i], Th = shtw[i + 512u];
        uint4 x0 = smem[tb + SZ(p)],       x1 = smem[tb + SZ(p + 32u)];
        uint4 x2 = smem[tb + SZ(p + 64u)], x3 = smem[tb + SZ(p + 96u)];
        bflyT(x0, x2, Ts); bflyT(x1, x3, Ts);
        bflyT(x0, x1, Tl); bflyT(x2, x3, Th);
        smem[tb + SZ(p)] = x0;       smem[tb + SZ(p + 32u)] = x1;
        smem[tb + SZ(p + 64u)] = x2; smem[tb + SZ(p + 96u)] = x3;
    }
    __syncthreads();

    // ---- P4: stages 7,8 (bits 4,3) --------------------------------------
    #pragma unroll 1
    for (int it = 0; it < 2; it++) {
        unsigned int u = m + ((unsigned)it << 8);
        unsigned int low = u & 7u, high = u >> 3;           // high < 64
        unsigned int p = (high << 5) | low;
        unsigned int i = (__brev(high) >> 26) << 3;
        unsigned int Ts = shtw[i << 1], Tl = shtw[i], Th = shtw[i + 512u];
        uint4 x0 = smem[tb + SZ(p)],       x1 = smem[tb + SZ(p + 8u)];
        uint4 x2 = smem[tb + SZ(p + 16u)], x3 = smem[tb + SZ(p + 24u)];
        bflyT(x0, x2, Ts); bflyT(x1, x3, Ts);
        bflyT(x0, x1, Tl); bflyT(x2, x3, Th);
        smem[tb + SZ(p)] = x0;       smem[tb + SZ(p + 8u)]  = x1;
        smem[tb + SZ(p + 16u)] = x2; smem[tb + SZ(p + 24u)] = x3;
    }
    __syncthreads();

    // ---- P5: stages 9,10 (bits 2,1); lane-enum hops high by 2 -----------
    #pragma unroll 1
    for (int it = 0; it < 2; it++) {
        unsigned int high = ((m >> 1) << 1) | (unsigned)it; // [0,256)
        unsigned int low  = m & 1u;
        unsigned int p = (high << 3) | low;
        unsigned int i = (__brev(high) >> 24) << 1;
        unsigned int Ts = shtw[i << 1], Tl = shtw[i], Th = shtw[i + 512u];
        uint4 x0 = smem[tb + SZ(p)],      x1 = smem[tb + SZ(p + 2u)];
        uint4 x2 = smem[tb + SZ(p + 4u)], x3 = smem[tb + SZ(p + 6u)];
        bflyT(x0, x2, Ts); bflyT(x1, x3, Ts);
        bflyT(x0, x1, Tl); bflyT(x2, x3, Th);
        smem[tb + SZ(p)] = x0;      smem[tb + SZ(p + 2u)] = x1;
        smem[tb + SZ(p + 4u)] = x2; smem[tb + SZ(p + 6u)] = x3;
    }
    __syncthreads();

    // ---- P6: stage 11 (bit 0) + paired scratch store --------------------
    const unsigned int b0 = __brev(rb0) >> 21;              // < 1024
    const unsigned int bj = b0 | (jt << 10);
    #pragma unroll 1
    for (int it = 0; it < 2; it++) {
        unsigned int v  = m + ((unsigned)it << 8);          // < 512
        unsigned int qv = __brev(v) >> 22;                  // rev10(v), even
        unsigned int Ta = shtw[qv], Tb = shtw[qv + 1u];
        uint4 a0 = smem[tb + SZ(2u * v)],          a1 = smem[tb + SZ(2u * v + 1u)];
        uint4 c0 = smem[tb + SZ(2u * v + 1024u)],  c1 = smem[tb + SZ(2u * v + 1025u)];
        bflyT(a0, a1, Ta);
        bflyT(c0, c1, Tb);
        size_t base = (((size_t)(2u * v) << 11) + bj) * 2u;
        g_scratch[base]          = a0;  g_scratch[base + 1]        = c0;
        g_scratch[base + 4096u]  = a1;  g_scratch[base + 4097u]    = c1;
    }
}

// ---------------------------------------------------------------------------
// Phase 2: stages 12..22 as twisted natural-order 2048-NTT per column.
// Half jt owns column C + jt*1024 (L = rev11(C)+jt).  Pass (sg,sg+1): quad
// base h has bits (sg-1),(sg) clear; i = (h mod 2^{sg-1}) << (10-sg);
// T_sg = shtw[i<<1], T_{sg+1} = shtw[i] / shtw[i+512].
// Twist slot 4u+d: exp = L*(rev9(u) + 512*rev2(d)); n_inv folded in.
// ---------------------------------------------------------------------------
__global__ void __launch_bounds__(512, 3) k_stage2(float4* __restrict__ out,
                                                   const unsigned int* __restrict__ tw,
                                                   const unsigned int* __restrict__ ni) {
    extern __shared__ uint4 smem[];
    unsigned int* shtw = (unsigned int*)(smem + 4096);

    const unsigned int tid = threadIdx.x;
    const unsigned int C   = blockIdx.x;
    const unsigned int L0  = __brev(C) >> 21;               // even
    const unsigned int jt  = tid >> 8, m = tid & 255u;
    const unsigned int tb  = jt << 11;
    const unsigned int L   = L0 + jt;

    // prefetch twist sources (overlap with staging)
    const unsigned int r9m = (__brev(m) >> 24) << 1;        // rev9(m) = 2*rev8(m)
    const unsigned int Fw0 = tw[(size_t)L * r9m];           // exp < 2^20
    const unsigned int Fw1 = tw[(size_t)L * (r9m + 1u)];
    const unsigned int Wb  = tw[(size_t)L << 9];            // exp < 2^20
    const unsigned int ni0 = ni[0];

    shtw[tid]        = mulmont(tw[(size_t)tid << 11], R2C);
    shtw[tid + 512u] = mulmont(tw[(size_t)(tid + 512u) << 11], R2C);
    __syncthreads();

    const unsigned int J  = shtw[512];
    const unsigned int X  = mulmont(mulmont(ni0, R2C), R2C);    // ninv * R^2
    const unsigned int W1 = mulmont(Wb, R2C);                   // mont(w^{-512L})
    const unsigned int W2 = mulmont(W1, W1);
    const unsigned int W3 = mulmont(W2, W1);

    // ---- P1': load + twist + stages 1,2 (strides 1,2) -------------------
    #pragma unroll 1
    for (int it = 0; it < 2; it++) {
        unsigned int u = m + ((unsigned)it << 8);           // [0,512)
        size_t sbase = (((size_t)C << 11) + 4u * u) * 2u + jt;
        uint4 x0 = g_scratch[sbase],     x1 = g_scratch[sbase + 2];
        uint4 x2 = g_scratch[sbase + 4], x3 = g_scratch[sbase + 6];
        unsigned int Fb = mulmont(it ? Fw1 : Fw0, X);
        unsigned int F1 = mulmont(Fb, W2), F2 = mulmont(Fb, W1), F3 = mulmont(Fb, W3);
        x0.x = mulmont(x0.x, Fb); x0.y = mulmont(x0.y, Fb);
        x0.z = mulmont(x0.z, Fb); x0.w = mulmont(x0.w, Fb);
        x1.x = mulmont(x1.x, F1); x1.y = mulmont(x1.y, F1);
        x1.z = mulmont(x1.z, F1); x1.w = mulmont(x1.w, F1);
        x2.x = mulmont(x2.x, F2); x2.y = mulmont(x2.y, F2);
        x2.z = mulmont(x2.z, F2); x2.w = mulmont(x2.w, F2);
        x3.x = mulmont(x3.x, F3); x3.y = mulmont(x3.y, F3);
        x3.z = mulmont(x3.z, F3); x3.w = mulmont(x3.w, F3);
        bfly1(x0, x1); bfly1(x2, x3);                       // sg=1
        bfly1(x0, x2); bflyT(x1, x3, J);                    // sg=2
        unsigned int h = 4u * u;
        smem[tb + SZ(h)] = x0;      smem[tb + SZ(h + 1u)] = x1;
        smem[tb + SZ(h + 2u)] = x2; smem[tb + SZ(h + 3u)] = x3;
    }
    __syncthreads();

    // ---- P2': stages 3,4 (strides 4,8) ----------------------------------
    #pragma unroll 1
    for (int it = 0; it < 2; it++) {
        unsigned int u = m + ((unsigned)it << 8);
        unsigned int low = u & 3u, high = u >> 2;           // high < 128
        unsigned int h = (high << 4) | low;
        unsigned int i = low << 7;
        unsigned int Ts = shtw[i << 1], Tl = shtw[i], Th = shtw[i + 512u];
        uint4 x0 = smem[tb + SZ(h)],      x1 = smem[tb + SZ(h + 4u)];
        uint4 x2 = smem[tb + SZ(h + 8u)], x3 = smem[tb + SZ(h + 12u)];
        bflyT(x0, x1, Ts); bflyT(x2, x3, Ts);
        bflyT(x0, x2, Tl); bflyT(x1, x3, Th);
        smem[tb + SZ(h)] = x0;      smem[tb + SZ(h + 4u)]  = x1;
        smem[tb + SZ(h + 8u)] = x2; smem[tb + SZ(h + 12u)] = x3;
    }
    __syncthreads();

    // ---- P3': stages 5,6 (strides 16,32) --------------------------------
    #pragma unroll 1
    for (int it = 0; it < 2; it++) {
        unsigned int u = m + ((unsigned)it << 8);
        unsigned int low = u & 15u, high = u >> 4;          // high < 32
        unsigned int h = (high << 6) | low;
        unsigned int i = low << 5;
        unsigned int Ts = shtw[i << 1], Tl = shtw[i], Th = shtw[i + 512u];
        uint4 x0 = smem[tb + SZ(h)],       x1 = smem[tb + SZ(h + 16u)];
        uint4 x2 = smem[tb + SZ(h + 32u)], x3 = smem[tb + SZ(h + 48u)];
        bflyT(x0, x1, Ts); bflyT(x2, x3, Ts);
        bflyT(x0, x2, Tl); bflyT(x1, x3, Th);
        smem[tb + SZ(h)] = x0;       smem[tb + SZ(h + 16u)] = x1;
        smem[tb + SZ(h + 32u)] = x2; smem[tb + SZ(h + 48u)] = x3;
    }
    __syncthreads();

    // ---- P4': stages 7,8 (strides 64,128) -------------------------------
    #pragma unroll 1
    for (int it = 0; it < 2; it++) {
        unsigned int u = m + ((unsigned)it << 8);
        unsigned int low = u & 63u, high = u >> 6;          // high < 8
        unsigned int h = (high << 8) | low;
        unsigned int i = low << 3;
        unsigned int Ts = shtw[i << 1], Tl = shtw[i], Th = shtw[i + 512u];
        uint4 x0 = smem[tb + SZ(h)],        x1 = smem[tb + SZ(h + 64u)];
        uint4 x2 = smem[tb + SZ(h + 128u)], x3 = smem[tb + SZ(h + 192u)];
        bflyT(x0, x1, Ts); bflyT(x2, x3, Ts);
        bflyT(x0, x2, Tl); bflyT(x1, x3, Th);
        smem[tb + SZ(h)] = x0;        smem[tb + SZ(h + 64u)]  = x1;
        smem[tb + SZ(h + 128u)] = x2; smem[tb + SZ(h + 192u)] = x3;
    }
    __syncthreads();

    // ---- P5': stages 9,10 (strides 256,512) -----------------------------
    #pragma unroll 1
    for (int it = 0; it < 2; it++) {
        unsigned int u = m + ((unsigned)it << 8);
        unsigned int low = u & 255u, high = u >> 8;         // high < 2
        unsigned int h = (high << 10) | low;
        unsigned int i = low << 1;
        unsigned int Ts = shtw[i << 1], Tl = shtw[i], Th = shtw[i + 512u];
        uint4 x0 = smem[tb + SZ(h)],        x1 = smem[tb + SZ(h + 256u)];
        uint4 x2 = smem[tb + SZ(h + 512u)], x3 = smem[tb + SZ(h + 768u)];
        bflyT(x0, x1, Ts); bflyT(x2, x3, Ts);
        bflyT(x0, x2, Tl); bflyT(x1, x3, Th);
        smem[tb + SZ(h)] = x0;        smem[tb + SZ(h + 256u)] = x1;
        smem[tb + SZ(h + 512u)] = x2; smem[tb + SZ(h + 768u)] = x3;
    }
    __syncthreads();

    // ---- P6': stage 11 (stride 1024) + output ---------------------------
    #pragma unroll 1
    for (int it = 0; it < 4; it++) {
        unsigned int hh = m + ((unsigned)it << 8);          // < 1024
        uint4 x0 = smem[tb + SZ(hh)];
        uint4 x1 = smem[tb + SZ(hh + 1024u)];
        bflyT(x0, x1, shtw[hh]);
        size_t row = ((size_t)hh << 11) | L;
        out[row] = make_float4((float)x0.x, (float)x0.y, (float)x0.z, (float)x0.w);
        out[row + ((size_t)1024u << 11)] =
            make_float4((float)x1.x, (float)x1.y, (float)x1.z, (float)x1.w);
    }
}

// ---------------------------------------------------------------------------

extern "C" void kernel_launch(void* const* d_in, const int* in_sizes, int n_in,
                              void* d_out, int out_size) {
    const void* p_in = (n_in > 0) ? d_in[0] : nullptr;
    const void* p_tw = (n_in > 1) ? d_in[1] : nullptr;
    const void* p_ni = (n_in > 2) ? d_in[2] : nullptr;
    for (int i = 0; i < n_in; i++) {
        unsigned int sz = (unsigned int)in_sizes[i];
        if (sz == NN * 4u) p_in = d_in[i];
        else if (sz == NH) p_tw = d_in[i];
        else if (sz == 1u) p_ni = d_in[i];
    }

    const int smem = 4096 * (int)sizeof(uint4) + 1024 * (int)sizeof(unsigned int); // 69632
    cudaFuncSetAttribute(k_stage1, cudaFuncAttributeMaxDynamicSharedMemorySize, smem);
    cudaFuncSetAttribute(k_stage2, cudaFuncAttributeMaxDynamicSharedMemorySize, smem);

    k_stage1<<< 1024, 512, smem >>>((const uint4*)p_in, (const unsigned int*)p_tw);
    k_stage2<<< 1024, 512, smem >>>((float4*)d_out, (const unsigned int*)p_tw,
                                    (const unsigned int*)p_ni);
    (void)out_size;
}

// round 14
// speedup vs baseline: 1.0817x; 1.0817x over previous
#include <cuda_runtime.h>
#include <cstdint>

// ---------------------------------------------------------------------------
// Inverse NTT over F_P, P = 2013265921 = 15*2^27 + 1, N = 2^22, C = 4.
// int32 inputs, float32 output (confirmed rel_err == 0).
//
// Two-phase NTT, radix-8/4 passes in swizzled shared memory (uint4 lanes),
// PERSISTENT blocks (grid 304) with an atomic tile ticket:
//   - twiddle staging + Montgomery conversion hoisted out of the tile loop
//   - near-perfect tile balance, CTAs drift out of phase across tiles
//   phase 1: staged gather | R8 | R4 | R8 | R8 | staged scratch store
//   phase 2: load+twist | R8 | R4 | R8 | R8 | output store
// ---------------------------------------------------------------------------

#define LOGN 22
#define NN   (1u << LOGN)
#define NH   (1u << (LOGN - 1))
#define NTILES 1024u
#define NBLK   304

static constexpr unsigned int P        = 2013265921u;
static constexpr unsigned int PINV_NEG = 2013265919u;                  // -P^{-1} mod 2^32
static constexpr unsigned long long Rmod = (1ull << 32) % P;
static constexpr unsigned int R2C = (unsigned int)((Rmod * Rmod) % P); // 2^64 mod P

// Scratch: phase-1 tile-row b, slot v at ((v&1023)<<11 + b)*2 + (v>>10).
static __device__ uint4 g_scratch[NN];   // 64 MB
static __device__ unsigned int g_ctr1;
static __device__ unsigned int g_ctr2;

__device__ __forceinline__ unsigned int SZ(unsigned int p) {
    return p ^ ((p >> 3) & 7u);
}
__device__ __forceinline__ unsigned int mulmont(unsigned int a, unsigned int bR) {
    unsigned long long t = (unsigned long long)a * bR;
    unsigned int m = (unsigned int)t * PINV_NEG;
    unsigned long long s = t + (unsigned long long)m * P;
    unsigned int r = (unsigned int)(s >> 32);
    return (r >= P) ? r - P : r;
}
__device__ __forceinline__ unsigned int addmod(unsigned int a, unsigned int b) {
    unsigned int r = a + b;  return min(r, r - P);
}
__device__ __forceinline__ unsigned int submod(unsigned int a, unsigned int b) {
    unsigned int r = a - b;  return min(r, r + P);
}
__device__ __forceinline__ void bflyT(uint4& lo, uint4& hi, unsigned int T) {
    unsigned int t0 = mulmont(hi.x, T), t1 = mulmont(hi.y, T);
    unsigned int t2 = mulmont(hi.z, T), t3 = mulmont(hi.w, T);
    uint4 l = lo;
    lo = make_uint4(addmod(l.x, t0), addmod(l.y, t1), addmod(l.z, t2), addmod(l.w, t3));
    hi = make_uint4(submod(l.x, t0), submod(l.y, t1), submod(l.z, t2), submod(l.w, t3));
}
__device__ __forceinline__ void bfly1(uint4& lo, uint4& hi) {
    uint4 l = lo, h = hi;
    lo = make_uint4(addmod(l.x, h.x), addmod(l.y, h.y), addmod(l.z, h.z), addmod(l.w, h.w));
    hi = make_uint4(submod(l.x, h.x), submod(l.y, h.y), submod(l.z, h.z), submod(l.w, h.w));
}

__global__ void k_reset() {
    g_ctr1 = 0u;
    g_ctr2 = 0u;
}

// ---------------------------------------------------------------------------
// Phase 1: gather + stages 1..11 on 2048-slot tiles in bit-reversed storage.
// ---------------------------------------------------------------------------
__global__ void __launch_bounds__(512) k_stage1(const uint4* __restrict__ in,
                                                const unsigned int* __restrict__ tw) {
    extern __shared__ uint4 smem[];                 // 2 tiles of 2048 + shtw
    unsigned int* shtw = (unsigned int*)(smem + 4096);
    __shared__ unsigned int sh_t;

    const unsigned int tid = threadIdx.x;
    const unsigned int jt  = tid >> 8, m = tid & 255u;
    const unsigned int tb  = jt << 11;

    // ---- hoisted: stage + Montgomery-convert the decimated twiddle set ---
    shtw[tid]        = mulmont(tw[(size_t)tid << 11], R2C);
    shtw[tid + 512u] = mulmont(tw[(size_t)(tid + 512u) << 11], R2C);

    for (;;) {
        if (tid == 0) sh_t = atomicAdd(&g_ctr1, 1u);
        __syncthreads();                            // ticket + smem reuse fence
        const unsigned int tile = sh_t;
        if (tile >= NTILES) break;
        const unsigned int rb0 = 2u * tile;

        // staged gather: 32B per thread-row (both tiles)
        #pragma unroll
        for (int r = 0; r < 4; r++) {
            unsigned int p = tid + r * 512u;
            size_t row = ((size_t)p << 11) | rb0;
            smem[SZ(p)]         = in[row];
            smem[2048u + SZ(p)] = in[row + 1];
        }
        __syncthreads();

        uint4 x[8];
        // ---- R8a: stages 1,2,3 (bits 10,9,8); slots m + k*256 -----------
        {
            #pragma unroll
            for (int k = 0; k < 8; k++) x[k] = smem[tb + SZ(m + (k << 8))];
            const unsigned int J  = shtw[512], K1 = shtw[256], K3 = shtw[768];
            bfly1(x[0], x[4]); bfly1(x[1], x[5]); bfly1(x[2], x[6]); bfly1(x[3], x[7]);
            bfly1(x[0], x[2]); bfly1(x[1], x[3]);
            bflyT(x[4], x[6], J); bflyT(x[5], x[7], J);
            bfly1(x[0], x[1]); bflyT(x[2], x[3], J);
            bflyT(x[4], x[5], K1); bflyT(x[6], x[7], K3);
            #pragma unroll
            for (int k = 0; k < 8; k++) smem[tb + SZ(m + (k << 8))] = x[k];
        }
        __syncthreads();

        // ---- R4: stages 4,5 (bits 7,6); quads {p0,+64,+128,+192} --------
        {
            const unsigned int lo = tid & 63u, hi = tid >> 6;      // hi < 8
            const unsigned int p0 = (hi << 8) | lo;
            const unsigned int i  = (__brev(hi) >> 29) << 6;       // rev3(hi)<<6
            const unsigned int T4 = shtw[i << 1], T5a = shtw[i], T5b = shtw[i + 512u];
            #pragma unroll
            for (int t = 0; t < 2; t++) {
                const unsigned int b = t << 11;
                uint4 x0 = smem[b + SZ(p0)],        x1 = smem[b + SZ(p0 + 64u)];
                uint4 x2 = smem[b + SZ(p0 + 128u)], x3 = smem[b + SZ(p0 + 192u)];
                bflyT(x0, x2, T4); bflyT(x1, x3, T4);              // s=4 (diff 128)
                bflyT(x0, x1, T5a); bflyT(x2, x3, T5b);            // s=5 (diff 64)
                smem[b + SZ(p0)] = x0;        smem[b + SZ(p0 + 64u)]  = x1;
                smem[b + SZ(p0 + 128u)] = x2; smem[b + SZ(p0 + 192u)] = x3;
            }
        }
        __syncthreads();

        // ---- R8b: stages 6,7,8 (bits 5,4,3); slots vb + k*8 -------------
        {
            const unsigned int lo3 = m & 7u, hi = m >> 3;          // hi < 32
            const unsigned int vb  = (hi << 6) | lo3;
            #pragma unroll
            for (int k = 0; k < 8; k++) x[k] = smem[tb + SZ(vb + (k << 3))];
            const unsigned int i   = (__brev(hi) >> 27) << 5;      // rev5(hi)<<5
            const unsigned int TA  = shtw[i];
            const unsigned int TB0 = shtw[i >> 1], TB1 = shtw[(i >> 1) + 512u];
            const unsigned int ib  = i >> 2;
            const unsigned int TC0 = shtw[ib],        TC1 = shtw[ib + 512u];
            const unsigned int TC2 = shtw[ib + 256u], TC3 = shtw[ib + 768u];
            bflyT(x[0], x[4], TA); bflyT(x[1], x[5], TA);
            bflyT(x[2], x[6], TA); bflyT(x[3], x[7], TA);
            bflyT(x[0], x[2], TB0); bflyT(x[1], x[3], TB0);
            bflyT(x[4], x[6], TB1); bflyT(x[5], x[7], TB1);
            bflyT(x[0], x[1], TC0); bflyT(x[2], x[3], TC1);
            bflyT(x[4], x[5], TC2); bflyT(x[6], x[7], TC3);
            #pragma unroll
            for (int k = 0; k < 8; k++) smem[tb + SZ(vb + (k << 3))] = x[k];
        }
        __syncthreads();

        // ---- R8c: stages 9,10,11 (bits 2,1,0); slots 8m+k ---------------
        {
            #pragma unroll
            for (int k = 0; k < 8; k++) x[k] = smem[tb + SZ(8u * m + k)];
            const unsigned int i   = (__brev(m) >> 24) << 2;       // rev8(m)<<2
            const unsigned int TA  = shtw[i];
            const unsigned int TB0 = shtw[i >> 1], TB1 = shtw[(i >> 1) + 512u];
            const unsigned int ib  = i >> 2;
            const unsigned int TC0 = shtw[ib],        TC1 = shtw[ib + 512u];
            const unsigned int TC2 = shtw[ib + 256u], TC3 = shtw[ib + 768u];
            bflyT(x[0], x[4], TA); bflyT(x[1], x[5], TA);
            bflyT(x[2], x[6], TA); bflyT(x[3], x[7], TA);
            bflyT(x[0], x[2], TB0); bflyT(x[1], x[3], TB0);
            bflyT(x[4], x[6], TB1); bflyT(x[5], x[7], TB1);
            bflyT(x[0], x[1], TC0); bflyT(x[2], x[3], TC1);
            bflyT(x[4], x[5], TC2); bflyT(x[6], x[7], TC3);
            #pragma unroll
            for (int k = 0; k < 8; k++) smem[tb + SZ(8u * m + k)] = x[k];
        }
        __syncthreads();

        // ---- staged store: paired 32B rows into scratch -----------------
        const unsigned int b0 = __brev(rb0) >> 21;     // < 1024
        const unsigned int b1 = b0 | 1024u;
        #pragma unroll
        for (int rr = 0; rr < 2; rr++) {
            unsigned int p = tid + rr * 512u;          // < 1024
            size_t base = ((size_t)p << 11);
            g_scratch[(base + b0) * 2 + 0] = smem[SZ(p)];
            g_scratch[(base + b0) * 2 + 1] = smem[SZ(p + 1024u)];
            g_scratch[(base + b1) * 2 + 0] = smem[2048u + SZ(p)];
            g_scratch[(base + b1) * 2 + 1] = smem[2048u + SZ(p + 1024u)];
        }
    }
}

// ---------------------------------------------------------------------------
// Phase 2: stages 12..22 as twisted natural-order 2048-NTT per column.
// Tile C: columns C (tile 0, L0 = rev11(C), even) and C+1024 (tile 1, L0+1).
// Twist w^{-L*rev11(h)} * n_inv folded into load (raw table value enters
// exactly once; X = ninv * R^2 supplies the Montgomery lift).
// ---------------------------------------------------------------------------
__global__ void __launch_bounds__(512) k_stage2(float4* __restrict__ out,
                                                const unsigned int* __restrict__ tw,
                                                const unsigned int* __restrict__ ni) {
    extern __shared__ uint4 smem[];
    unsigned int* shtw = (unsigned int*)(smem + 4096);
    __shared__ unsigned int sh_t;

    const unsigned int tid = threadIdx.x;

    // ---- hoisted staging + constants -------------------------------------
    shtw[tid]        = mulmont(tw[(size_t)tid << 11], R2C);
    shtw[tid + 512u] = mulmont(tw[(size_t)(tid + 512u) << 11], R2C);
    const unsigned int X  = mulmont(mulmont(ni[0], R2C), R2C);   // ninv * R^2
    const unsigned int r9 = __brev(tid) >> 23;                   // rev9(tid)

    for (;;) {
        if (tid == 0) sh_t = atomicAdd(&g_ctr2, 1u);
        __syncthreads();                            // ticket + smem reuse fence
        const unsigned int C = sh_t;
        if (C >= NTILES) break;
        const unsigned int L0 = __brev(C) >> 21;    // even
        const unsigned int L1 = L0 + 1u;

        // uniform twist corrections (exp < 3*2048 << 2^21: no sign fold)
        const unsigned int W0_1 = mulmont(tw[L0], R2C),      W1_1 = mulmont(tw[L1], R2C);
        const unsigned int W0_2 = mulmont(tw[2u * L0], R2C), W1_2 = mulmont(tw[2u * L1], R2C);
        const unsigned int W0_3 = mulmont(tw[3u * L0], R2C), W1_3 = mulmont(tw[3u * L1], R2C);

        unsigned int Fb0, Fb1;
        {
            unsigned int e0 = 4u * L0 * r9;         // < 2^22
            unsigned int v0 = tw[e0 & (NH - 1u)];
            if (e0 & NH) v0 = P - v0;               // w^{-2^21} = -1
            Fb0 = mulmont(v0, X);                   // = mont(w^{-e0} * ninv)
            unsigned int e1 = 4u * L1 * r9;
            unsigned int v1 = tw[e1 & (NH - 1u)];
            if (e1 & NH) v1 = P - v1;
            Fb1 = mulmont(v1, X);
        }

        #pragma unroll
        for (int k = 0; k < 4; k++) {
            unsigned int h = tid + k * 512u;
            size_t base = (((size_t)C << 11) + h) * 2;
            uint4 z0 = g_scratch[base];
            uint4 z1 = g_scratch[base + 1];
            unsigned int f0, f1;                     // correction exp = rev2(k)
            if      (k == 0) { f0 = Fb0;                f1 = Fb1;                }
            else if (k == 1) { f0 = mulmont(Fb0, W0_2); f1 = mulmont(Fb1, W1_2); }
            else if (k == 2) { f0 = mulmont(Fb0, W0_1); f1 = mulmont(Fb1, W1_1); }
            else             { f0 = mulmont(Fb0, W0_3); f1 = mulmont(Fb1, W1_3); }
            smem[SZ(h)] = make_uint4(mulmont(z0.x, f0), mulmont(z0.y, f0),
                                     mulmont(z0.z, f0), mulmont(z0.w, f0));
            smem[2048u + SZ(h)] = make_uint4(mulmont(z1.x, f1), mulmont(z1.y, f1),
                                             mulmont(z1.z, f1), mulmont(z1.w, f1));
        }
        __syncthreads();

        const unsigned int jt = tid >> 8, m = tid & 255u;
        const unsigned int tb = jt << 11;
        uint4 x[8];

        // ---- R8a: sg 1,2,3 (strides 1,2,4); slots 8m + k ----------------
        {
            #pragma unroll
            for (int k = 0; k < 8; k++) x[k] = smem[tb + SZ(8u * m + k)];
            const unsigned int J = shtw[512], K1 = shtw[256], K3 = shtw[768];
            bfly1(x[0], x[1]); bfly1(x[2], x[3]); bfly1(x[4], x[5]); bfly1(x[6], x[7]);
            bfly1(x[0], x[2]); bflyT(x[1], x[3], J);
            bfly1(x[4], x[6]); bflyT(x[5], x[7], J);
            bfly1(x[0], x[4]); bflyT(x[1], x[5], K1);
            bflyT(x[2], x[6], J); bflyT(x[3], x[7], K3);
            #pragma unroll
            for (int k = 0; k < 8; k++) smem[tb + SZ(8u * m + k)] = x[k];
        }
        __syncthreads();

        // ---- R4: sg 4,5 (strides 8,16); quads {h0,+8,+16,+24} -----------
        {
            const unsigned int lo3 = tid & 7u, hi = tid >> 3;      // hi < 64
            const unsigned int h0  = (hi << 5) | lo3;
            const unsigned int i   = lo3 << 6;
            const unsigned int T4 = shtw[i << 1], T5a = shtw[i], T5b = shtw[i + 512u];
            #pragma unroll
            for (int t = 0; t < 2; t++) {
                const unsigned int b = t << 11;
                uint4 x0 = smem[b + SZ(h0)],        x1 = smem[b + SZ(h0 + 8u)];
                uint4 x2 = smem[b + SZ(h0 + 16u)],  x3 = smem[b + SZ(h0 + 24u)];
                bflyT(x0, x1, T4); bflyT(x2, x3, T4);              // sg=4
                bflyT(x0, x2, T5a); bflyT(x1, x3, T5b);            // sg=5
                smem[b + SZ(h0)] = x0;        smem[b + SZ(h0 + 8u)]  = x1;
                smem[b + SZ(h0 + 16u)] = x2;  smem[b + SZ(h0 + 24u)] = x3;
            }
        }
        __syncthreads();

        // ---- R8b: sg 6,7,8 (strides 32,64,128); slots vb + k*32 ---------
        {
            const unsigned int lo5 = m & 31u, hi = m >> 5;         // hi < 8
            const unsigned int vb  = (hi << 8) | lo5;
            #pragma unroll
            for (int k = 0; k < 8; k++) x[k] = smem[tb + SZ(vb + (k << 5))];
            const unsigned int i   = lo5 << 5;
            const unsigned int TA  = shtw[i];
            const unsigned int TB0 = shtw[i >> 1], TB1 = shtw[(i >> 1) + 512u];
            const unsigned int ib  = i >> 2;
            const unsigned int TC0 = shtw[ib],        TC1 = shtw[ib + 256u];
            const unsigned int TC2 = shtw[ib + 512u], TC3 = shtw[ib + 768u];
            bflyT(x[0], x[1], TA); bflyT(x[2], x[3], TA);
            bflyT(x[4], x[5], TA); bflyT(x[6], x[7], TA);
            bflyT(x[0], x[2], TB0); bflyT(x[1], x[3], TB1);
            bflyT(x[4], x[6], TB0); bflyT(x[5], x[7], TB1);
            bflyT(x[0], x[4], TC0); bflyT(x[1], x[5], TC1);
            bflyT(x[2], x[6], TC2); bflyT(x[3], x[7], TC3);
            #pragma unroll
            for (int k = 0; k < 8; k++) smem[tb + SZ(vb + (k << 5))] = x[k];
        }
        __syncthreads();

        // ---- R8c: sg 9,10,11 (strides 256,512,1024); slots k*256+m ------
        {
            #pragma unroll
            for (int k = 0; k < 8; k++) x[k] = smem[tb + SZ((k << 8) + m)];
            const unsigned int i   = m << 2;
            const unsigned int TA  = shtw[i];
            const unsigned int TB0 = shtw[i >> 1], TB1 = shtw[(i >> 1) + 512u];
            const unsigned int TC0 = shtw[m],        TC1 = shtw[m + 256u];
            const unsigned int TC2 = shtw[m + 512u], TC3 = shtw[m + 768u];
            bflyT(x[0], x[1], TA); bflyT(x[2], x[3], TA);
            bflyT(x[4], x[5], TA); bflyT(x[6], x[7], TA);
            bflyT(x[0], x[2], TB0); bflyT(x[1], x[3], TB1);
            bflyT(x[4], x[6], TB0); bflyT(x[5], x[7], TB1);
            bflyT(x[0], x[4], TC0); bflyT(x[1], x[5], TC1);
            bflyT(x[2], x[6], TC2); bflyT(x[3], x[7], TC3);
            #pragma unroll
            for (int k = 0; k < 8; k++) smem[tb + SZ((k << 8) + m)] = x[k];
        }
        __syncthreads();

        // ---- store: adjacent column pair -> 32B float4 x2 ---------------
        #pragma unroll
        for (int k = 0; k < 4; k++) {
            unsigned int h = tid + k * 512u;
            uint4 v0 = smem[SZ(h)];
            uint4 v1 = smem[2048u + SZ(h)];
            size_t row = ((size_t)h << 11) | L0;
            out[row]     = make_float4((float)v0.x, (float)v0.y, (float)v0.z, (float)v0.w);
            out[row + 1] = make_float4((float)v1.x, (float)v1.y, (float)v1.z, (float)v1.w);
        }
    }
}

// ---------------------------------------------------------------------------

extern "C" void kernel_launch(void* const* d_in, const int* in_sizes, int n_in,
                              void* d_out, int out_size) {
    const void* p_in = (n_in > 0) ? d_in[0] : nullptr;
    const void* p_tw = (n_in > 1) ? d_in[1] : nullptr;
    const void* p_ni = (n_in > 2) ? d_in[2] : nullptr;
    for (int i = 0; i < n_in; i++) {
        unsigned int sz = (unsigned int)in_sizes[i];
        if (sz == NN * 4u) p_in = d_in[i];
        else if (sz == NH) p_tw = d_in[i];
        else if (sz == 1u) p_ni = d_in[i];
    }

    const int smem = 4096 * (int)sizeof(uint4) + 1024 * (int)sizeof(unsigned int); // 69632
    cudaFuncSetAttribute(k_stage1, cudaFuncAttributeMaxDynamicSharedMemorySize, smem);
    cudaFuncSetAttribute(k_stage2, cudaFuncAttributeMaxDynamicSharedMemorySize, smem);

    k_reset <<< 1, 1 >>>();
    k_stage1<<< NBLK, 512, smem >>>((const uint4*)p_in, (const unsigned int*)p_tw);
    k_stage2<<< NBLK, 512, smem >>>((float4*)d_out, (const unsigned int*)p_tw,
                                    (const unsigned int*)p_ni);
    (void)out_size;
}